// round 6
// baseline (speedup 1.0000x reference)
#include <cuda_runtime.h>
#include <math.h>

#define H 1024
#define V 50257
#define L 128
#define OUT_ROWS 16
#define GOUT ((V + OUT_ROWS - 1) / OUT_ROWS)   // 3142 blocks
#define CACHE_ROWS 16384                        // out_W rows kept L2-cacheable (64MB)

// ---- scratch (no allocations allowed), 16B-aligned for float4 access ----
__device__ __align__(16) float g_attn_scratch[L];   // logits, then weights
__device__ __align__(16) float g_attn_applied[H];
__device__ __align__(16) float g_x[H];              // relu(comb) output
__device__ __align__(16) float g_h[H];              // new hidden (aligned copy)
__device__ __align__(16) float g_logits[V + 3];
__device__ __align__(16) float g_bmax[GOUT];
__device__ __align__(16) float g_bsum[GOUT];
__device__ float    g_logZ;
__device__ unsigned g_ctr_attn = 0;
__device__ unsigned g_ctr_out  = 0;

__device__ __forceinline__ float warp_sum(float v) {
    #pragma unroll
    for (int o = 16; o; o >>= 1) v += __shfl_down_sync(0xffffffffu, v, o);
    return v;
}
__device__ __forceinline__ float warp_max(float v) {
    #pragma unroll
    for (int o = 16; o; o >>= 1) v = fmaxf(v, __shfl_down_sync(0xffffffffu, v, o));
    return v;
}
__device__ __forceinline__ float dot4(float4 a, float4 b) {
    return a.x * b.x + a.y * b.y + a.z * b.z + a.w * b.w;
}

// ---------------------------------------------------------------------------
// attn logits (block per row) + fused softmax in last arriving block
// attn_W is small (1MB) -> cacheable, hits L2 on replays.
// ---------------------------------------------------------------------------
__global__ void k_attn(const int* __restrict__ tokens,
                       const float* __restrict__ emb,
                       const float* __restrict__ h0,
                       const float* __restrict__ attn_W,
                       const float* __restrict__ attn_b,
                       float* __restrict__ attn_w_out) {
    int l = blockIdx.x;
    const float4* erow = (const float4*)(emb + (long)tokens[0] * H);
    const float4* hrow = (const float4*)h0;
    const float4* w    = (const float4*)(attn_W + (long)l * 2 * H);
    float acc = 0.f;
    for (int i = threadIdx.x; i < 2 * H / 4; i += blockDim.x) {
        float4 wv = w[i];
        float4 xv = (i < H / 4) ? erow[i] : hrow[i - H / 4];
        acc += dot4(wv, xv);
    }
    __shared__ float s[8];
    acc = warp_sum(acc);
    if ((threadIdx.x & 31) == 0) s[threadIdx.x >> 5] = acc;
    __syncthreads();
    __shared__ unsigned is_last;
    if (threadIdx.x == 0) {
        float v = 0.f;
        #pragma unroll
        for (int k = 0; k < 8; k++) v += s[k];
        g_attn_scratch[l] = v + attn_b[l];
        __threadfence();
        is_last = (atomicAdd(&g_ctr_attn, 1u) == L - 1);
    }
    __syncthreads();
    if (!is_last) return;

    // ---- last block: softmax over 128 logits ----
    __threadfence();
    __shared__ float sm[L];
    int t = threadIdx.x;
    float v = 0.f;
    if (t < L) { v = g_attn_scratch[t]; sm[t] = v; }
    __syncthreads();
    if (t < L) {
        for (int st = 64; st; st >>= 1) { if (t < st) sm[t] = fmaxf(sm[t], sm[t + st]); __syncthreads(); }
    } else { for (int st = 64; st; st >>= 1) __syncthreads(); }
    float m = sm[0]; __syncthreads();
    float e = (t < L) ? expf(v - m) : 0.f;
    if (t < L) sm[t] = e;
    __syncthreads();
    if (t < L) {
        for (int st = 64; st; st >>= 1) { if (t < st) sm[t] += sm[t + st]; __syncthreads(); }
    } else { for (int st = 64; st; st >>= 1) __syncthreads(); }
    if (t < L) {
        float wgt = e / sm[0];
        attn_w_out[t]     = wgt;
        g_attn_scratch[t] = wgt;
    }
    if (t == 0) g_ctr_attn = 0;   // reset for next graph replay
}

// ---------------------------------------------------------------------------
// attn_applied[j] = sum_l w[l] * enc[l][j]    (enc 512KB, cacheable)
// ---------------------------------------------------------------------------
__global__ void k_attn_applied(const float* __restrict__ enc) {
    int t  = threadIdx.x;
    int jl = t & 31, lg = t >> 5;
    int j  = blockIdx.x * 32 + jl;
    float acc = 0.f;
    #pragma unroll
    for (int k = 0; k < 16; k++) {
        int l = lg * 16 + k;
        acc += g_attn_scratch[l] * enc[l * H + j];
    }
    __shared__ float s[8][32];
    s[lg][jl] = acc;
    __syncthreads();
    if (lg == 0) {
        float v = acc;
        #pragma unroll
        for (int k = 1; k < 8; k++) v += s[k][jl];
        g_attn_applied[j] = v;
    }
}

// ---------------------------------------------------------------------------
// x = relu(comb_W @ [embedded||attn_applied] + comb_b)   (8MB, cacheable)
// ---------------------------------------------------------------------------
__global__ void k_comb(const int* __restrict__ tokens,
                       const float* __restrict__ emb,
                       const float* __restrict__ comb_W,
                       const float* __restrict__ comb_b) {
    int warp = threadIdx.x >> 5, lane = threadIdx.x & 31;
    int row = blockIdx.x * 8 + warp;
    const float4* erow = (const float4*)(emb + (long)tokens[0] * H);
    const float4* arow = (const float4*)g_attn_applied;
    const float4* w    = (const float4*)(comb_W + (long)row * 2 * H);
    float4 wr[16];
    #pragma unroll
    for (int k = 0; k < 16; k++) wr[k] = w[lane + 32 * k];
    float acc = 0.f;
    #pragma unroll
    for (int k = 0; k < 16; k++) {
        int i = lane + 32 * k;
        float4 xv = (i < 256) ? erow[i] : arow[i - 256];
        acc += dot4(wr[k], xv);
    }
    acc = warp_sum(acc);
    if (lane == 0) g_x[row] = fmaxf(acc + comb_b[row], 0.f);
}

// ---------------------------------------------------------------------------
// LSTM cell: 1024 blocks x 128 thr. Weights (32MB) cacheable -> L2 on replays.
// ---------------------------------------------------------------------------
__global__ void __launch_bounds__(128) k_lstm(
        const float* __restrict__ W_ih, const float* __restrict__ W_hh,
        const float* __restrict__ b_ih, const float* __restrict__ b_hh,
        const float* __restrict__ h0,   const float* __restrict__ c0,
        float* __restrict__ h_out, float* __restrict__ c_out) {
    int tid  = threadIdx.x;
    int gate = tid >> 5, lane = tid & 31;
    int j    = blockIdx.x;
    int r    = gate * H + j;

    const float4* wi = (const float4*)(W_ih + (long)r * H);
    const float4* wh = (const float4*)(W_hh + (long)r * H);

    float4 va[8], vb[8];
    #pragma unroll
    for (int k = 0; k < 8; k++) va[k] = wi[lane + 32 * k];
    #pragma unroll
    for (int k = 0; k < 8; k++) vb[k] = wh[lane + 32 * k];

    __shared__ float4 sx[H / 4];
    __shared__ float4 sh[H / 4];
    #pragma unroll
    for (int k = 0; k < 2; k++) {
        sx[tid + 128 * k] = ((const float4*)g_x)[tid + 128 * k];
        sh[tid + 128 * k] = ((const float4*)h0)[tid + 128 * k];
    }
    __syncthreads();

    float a1 = 0.f, a2 = 0.f;
    #pragma unroll
    for (int k = 0; k < 8; k++) {
        a1 += dot4(va[k], sx[lane + 32 * k]);
        a2 += dot4(vb[k], sh[lane + 32 * k]);
    }
    float acc = warp_sum(a1 + a2);
    __shared__ float g[4];
    if (lane == 0) g[gate] = acc + b_ih[r] + b_hh[r];
    __syncthreads();
    if (tid == 0) {
        float ig = 1.f / (1.f + expf(-g[0]));
        float fg = 1.f / (1.f + expf(-g[1]));
        float gg = tanhf(g[2]);
        float og = 1.f / (1.f + expf(-g[3]));
        float cn = fg * c0[j] + ig * gg;
        float hn = og * tanhf(cn);
        c_out[j] = cn;
        h_out[j] = hn;
        g_h[j]   = hn;
    }
}

// ---------------------------------------------------------------------------
// output projection: rows < CACHE_ROWS use default (cacheable) loads -> L2
// resident across graph replays; the rest use __ldcs (evict-first streaming)
// so they never displace the pinned set. Fused logZ via last-block reduce.
// ---------------------------------------------------------------------------
__global__ void __launch_bounds__(256) k_out(const float* __restrict__ out_W,
                                             const float* __restrict__ out_b) {
    __shared__ float4 sh4[H / 4];
    __shared__ float  slog[OUT_ROWS];
    sh4[threadIdx.x] = ((const float4*)g_h)[threadIdx.x];
    __syncthreads();

    int warp = threadIdx.x >> 5, lane = threadIdx.x & 31;
    int row0 = blockIdx.x * OUT_ROWS + warp * 2;
    int row1 = row0 + 1;
    bool v0 = row0 < V, v1 = row1 < V;
    int r0c = v0 ? row0 : V - 1;
    int r1c = v1 ? row1 : V - 1;
    const float4* w0 = (const float4*)(out_W + (long)r0c * H);
    const float4* w1 = (const float4*)(out_W + (long)r1c * H);

    float4 wa[8], wb[8];
    if (row0 < CACHE_ROWS) {          // warp-uniform branch
        #pragma unroll
        for (int k = 0; k < 8; k++) wa[k] = w0[lane + 32 * k];
        #pragma unroll
        for (int k = 0; k < 8; k++) wb[k] = w1[lane + 32 * k];
    } else {
        #pragma unroll
        for (int k = 0; k < 8; k++) wa[k] = __ldcs(w0 + lane + 32 * k);
        #pragma unroll
        for (int k = 0; k < 8; k++) wb[k] = __ldcs(w1 + lane + 32 * k);
    }

    float a0 = 0.f, a1 = 0.f;
    #pragma unroll
    for (int k = 0; k < 8; k++) {
        float4 hv = sh4[lane + 32 * k];
        a0 += dot4(wa[k], hv);
        a1 += dot4(wb[k], hv);
    }
    a0 = warp_sum(a0);
    a1 = warp_sum(a1);
    if (lane == 0) {
        float l0 = v0 ? a0 + out_b[row0] : -INFINITY;
        float l1 = v1 ? a1 + out_b[row1] : -INFINITY;
        if (v0) g_logits[row0] = l0;
        if (v1) g_logits[row1] = l1;
        slog[warp * 2]     = l0;
        slog[warp * 2 + 1] = l1;
    }
    __syncthreads();
    __shared__ unsigned is_last;
    if (threadIdx.x == 0) {
        float m = slog[0];
        #pragma unroll
        for (int k = 1; k < OUT_ROWS; k++) m = fmaxf(m, slog[k]);
        float s = 0.f;
        #pragma unroll
        for (int k = 0; k < OUT_ROWS; k++) s += expf(slog[k] - m);
        g_bmax[blockIdx.x] = m;
        g_bsum[blockIdx.x] = s;
        __threadfence();
        is_last = (atomicAdd(&g_ctr_out, 1u) == GOUT - 1);
    }
    __syncthreads();
    if (!is_last) return;

    // ---- last block: reduce 3142 (max,sum) pairs ----
    __threadfence();
    int t = threadIdx.x;
    float m = -INFINITY;
    for (int k = t; k < GOUT; k += 256) m = fmaxf(m, g_bmax[k]);
    __shared__ float sred[8];
    m = warp_max(m);
    if (lane == 0) sred[warp] = m;
    __syncthreads();
    if (t == 0) {
        float mm = sred[0];
        #pragma unroll
        for (int k = 1; k < 8; k++) mm = fmaxf(mm, sred[k]);
        sred[0] = mm;
    }
    __syncthreads();
    m = sred[0];
    __syncthreads();
    float s = 0.f;
    for (int k = t; k < GOUT; k += 256) s += g_bsum[k] * expf(g_bmax[k] - m);
    s = warp_sum(s);
    if (lane == 0) sred[warp] = s;
    __syncthreads();
    if (t == 0) {
        float ss = 0.f;
        #pragma unroll
        for (int k = 0; k < 8; k++) ss += sred[k];
        g_logZ = m + logf(ss);
        g_ctr_out = 0;   // reset for next graph replay
    }
}

__global__ void k_final(float* __restrict__ out) {
    int v = blockIdx.x * blockDim.x + threadIdx.x;
    if (v >= V) return;
    out[v] = g_logits[v] - g_logZ;
}

extern "C" void kernel_launch(void* const* d_in, const int* in_sizes, int n_in,
                              void* d_out, int out_size) {
    const int*   tokens = (const int*)  d_in[0];
    const float* h0     = (const float*)d_in[1];
    const float* c0     = (const float*)d_in[2];
    const float* enc    = (const float*)d_in[3];
    const float* emb    = (const float*)d_in[4];
    const float* attn_W = (const float*)d_in[5];
    const float* attn_b = (const float*)d_in[6];
    const float* comb_W = (const float*)d_in[7];
    const float* comb_b = (const float*)d_in[8];
    const float* W_ih   = (const float*)d_in[9];
    const float* W_hh   = (const float*)d_in[10];
    const float* b_ih   = (const float*)d_in[11];
    const float* b_hh   = (const float*)d_in[12];
    const float* out_W  = (const float*)d_in[13];
    const float* out_b  = (const float*)d_in[14];

    float* out    = (float*)d_out;          // [V] log-probs
    float* h_out  = out + V;                // [H]
    float* c_out  = out + V + H;            // [H]
    float* aw_out = out + V + 2 * H;        // [L]

    k_attn        <<<L, 256>>>(tokens, emb, h0, attn_W, attn_b, aw_out);
    k_attn_applied<<<H / 32, 256>>>(enc);
    k_comb        <<<H / 8, 256>>>(tokens, emb, comb_W, comb_b);
    k_lstm        <<<H, 128>>>(W_ih, W_hh, b_ih, b_hh, h0, c0, h_out, c_out);
    k_out         <<<GOUT, 256>>>(out_W, out_b);
    k_final       <<<(V + 511) / 512, 512>>>(out);
}

// round 7
// speedup vs baseline: 1.1755x; 1.1755x over previous
#include <cuda_runtime.h>
#include <math.h>
#include <stdint.h>

#define H 1024
#define V 50257
#define L 128

#define OT_TILE 4
#define OT_NT   ((V + OT_TILE - 1) / OT_TILE)   // 12565 tiles
#define OT_GRID 888                              // 148 SMs x 6 resident

#define GT_TILE 4
#define GT_TILES 2048                            // 8192 rows / 4

// ---- scratch (no allocations allowed), 16B-aligned ----
__device__ __align__(16) float g_attn_scratch[L];
__device__ __align__(16) float g_attn_applied[H];
__device__ __align__(16) float g_x[H];
__device__ __align__(16) float g_h[H];
__device__ __align__(16) float g_gates[4 * H];
__device__ __align__(16) float g_bmax[OT_GRID];
__device__ __align__(16) float g_bsum[OT_GRID];
__device__ float    g_logZ;
__device__ unsigned g_ctr_attn = 0;
__device__ unsigned g_ctr_out  = 0;

__device__ __forceinline__ float warp_sum(float v) {
    #pragma unroll
    for (int o = 16; o; o >>= 1) v += __shfl_down_sync(0xffffffffu, v, o);
    return v;
}
__device__ __forceinline__ float warp_max(float v) {
    #pragma unroll
    for (int o = 16; o; o >>= 1) v = fmaxf(v, __shfl_down_sync(0xffffffffu, v, o));
    return v;
}
__device__ __forceinline__ float dot4(float4 a, float4 b) {
    return a.x * b.x + a.y * b.y + a.z * b.z + a.w * b.w;
}
__device__ __forceinline__ uint64_t mkpolicy() {
    uint64_t p;
    asm("createpolicy.fractional.L2::evict_first.b64 %0, 1.0;" : "=l"(p));
    return p;
}
__device__ __forceinline__ void cp16(float4* dst_smem, const float4* src, uint64_t pol) {
    unsigned s = (unsigned)__cvta_generic_to_shared(dst_smem);
    asm volatile("cp.async.cg.shared.global.L2::cache_hint [%0], [%1], 16, %2;"
                 :: "r"(s), "l"(src), "l"(pol));
}
#define CP_COMMIT() asm volatile("cp.async.commit_group;")
#define CP_WAIT(n)  asm volatile("cp.async.wait_group %0;" :: "n"(n))

// ---------------------------------------------------------------------------
// attn logits (block per row) + fused softmax in last arriving block
// ---------------------------------------------------------------------------
__global__ void k_attn(const int* __restrict__ tokens,
                       const float* __restrict__ emb,
                       const float* __restrict__ h0,
                       const float* __restrict__ attn_W,
                       const float* __restrict__ attn_b,
                       float* __restrict__ attn_w_out) {
    int l = blockIdx.x;
    const float4* erow = (const float4*)(emb + (long)tokens[0] * H);
    const float4* hrow = (const float4*)h0;
    const float4* w    = (const float4*)(attn_W + (long)l * 2 * H);
    float acc = 0.f;
    for (int i = threadIdx.x; i < 2 * H / 4; i += blockDim.x) {
        float4 wv = __ldcs(w + i);
        float4 xv = (i < H / 4) ? erow[i] : hrow[i - H / 4];
        acc += dot4(wv, xv);
    }
    __shared__ float s[8];
    acc = warp_sum(acc);
    if ((threadIdx.x & 31) == 0) s[threadIdx.x >> 5] = acc;
    __syncthreads();
    __shared__ unsigned is_last;
    if (threadIdx.x == 0) {
        float v = 0.f;
        #pragma unroll
        for (int k = 0; k < 8; k++) v += s[k];
        g_attn_scratch[l] = v + attn_b[l];
        __threadfence();
        is_last = (atomicAdd(&g_ctr_attn, 1u) == L - 1);
    }
    __syncthreads();
    if (!is_last) return;

    __threadfence();
    __shared__ float sm[L];
    int t = threadIdx.x;
    float v = 0.f;
    if (t < L) { v = g_attn_scratch[t]; sm[t] = v; }
    __syncthreads();
    if (t < L) {
        for (int st = 64; st; st >>= 1) { if (t < st) sm[t] = fmaxf(sm[t], sm[t + st]); __syncthreads(); }
    } else { for (int st = 64; st; st >>= 1) __syncthreads(); }
    float m = sm[0]; __syncthreads();
    float e = (t < L) ? expf(v - m) : 0.f;
    if (t < L) sm[t] = e;
    __syncthreads();
    if (t < L) {
        for (int st = 64; st; st >>= 1) { if (t < st) sm[t] += sm[t + st]; __syncthreads(); }
    } else { for (int st = 64; st; st >>= 1) __syncthreads(); }
    if (t < L) {
        float wgt = e / sm[0];
        attn_w_out[t]     = wgt;
        g_attn_scratch[t] = wgt;
    }
    if (t == 0) g_ctr_attn = 0;
}

// ---------------------------------------------------------------------------
// attn_applied[j] = sum_l w[l] * enc[l][j]
// ---------------------------------------------------------------------------
__global__ void k_attn_applied(const float* __restrict__ enc) {
    int t  = threadIdx.x;
    int jl = t & 31, lg = t >> 5;
    int j  = blockIdx.x * 32 + jl;
    float acc = 0.f;
    #pragma unroll
    for (int k = 0; k < 16; k++) {
        int l = lg * 16 + k;
        acc += g_attn_scratch[l] * enc[l * H + j];
    }
    __shared__ float s[8][32];
    s[lg][jl] = acc;
    __syncthreads();
    if (lg == 0) {
        float v = acc;
        #pragma unroll
        for (int k = 1; k < 8; k++) v += s[k][jl];
        g_attn_applied[j] = v;
    }
}

// ---------------------------------------------------------------------------
// x = relu(comb_W @ [embedded||attn_applied] + comb_b); also preset gate
// accumulators with biases (runs before k_gates).
// ---------------------------------------------------------------------------
__global__ void k_comb(const int* __restrict__ tokens,
                       const float* __restrict__ emb,
                       const float* __restrict__ comb_W,
                       const float* __restrict__ comb_b,
                       const float* __restrict__ b_ih,
                       const float* __restrict__ b_hh) {
    if (threadIdx.x < 32) {           // bias-preset: 128 blocks x 32 = 4096
        int gi = blockIdx.x * 32 + threadIdx.x;
        g_gates[gi] = b_ih[gi] + b_hh[gi];
    }
    int warp = threadIdx.x >> 5, lane = threadIdx.x & 31;
    int row = blockIdx.x * 8 + warp;
    const float4* erow = (const float4*)(emb + (long)tokens[0] * H);
    const float4* arow = (const float4*)g_attn_applied;
    const float4* w    = (const float4*)(comb_W + (long)row * 2 * H);
    float4 wr[16];
    #pragma unroll
    for (int k = 0; k < 16; k++) wr[k] = __ldcs(w + lane + 32 * k);
    float acc = 0.f;
    #pragma unroll
    for (int k = 0; k < 16; k++) {
        int i = lane + 32 * k;
        float4 xv = (i < 256) ? erow[i] : arow[i - 256];
        acc += dot4(wr[k], xv);
    }
    acc = warp_sum(acc);
    if (lane == 0) g_x[row] = fmaxf(acc + comb_b[row], 0.f);
}

// ---------------------------------------------------------------------------
// k_gates: stream W_ih (tiles 0..1023) and W_hh (tiles 1024..2047), 4 gate
// rows per tile, cp.async double-buffered; partial dot atomicAdd into g_gates.
// ---------------------------------------------------------------------------
__global__ void __launch_bounds__(128) k_gates(const float* __restrict__ W_ih,
                                               const float* __restrict__ W_hh,
                                               const float* __restrict__ h0) {
    __shared__ float4 buf[2][GT_TILE * 256];   // 2 x 16KB
    __shared__ float4 svx[256], svh[256];
    int tid = threadIdx.x, warp = tid >> 5, lane = tid & 31;
    uint64_t pol = mkpolicy();

    svx[tid]       = ((const float4*)g_x)[tid];
    svx[tid + 128] = ((const float4*)g_x)[tid + 128];
    svh[tid]       = ((const float4*)h0)[tid];
    svh[tid + 128] = ((const float4*)h0)[tid + 128];

    int t0 = blockIdx.x * 2, t1 = t0 + 1;
    const float4* s0 = (const float4*)((t0 < 1024) ? W_ih + (long)t0 * GT_TILE * H
                                                   : W_hh + (long)(t0 - 1024) * GT_TILE * H);
    const float4* s1 = (const float4*)((t1 < 1024) ? W_ih + (long)t1 * GT_TILE * H
                                                   : W_hh + (long)(t1 - 1024) * GT_TILE * H);
    #pragma unroll
    for (int k = 0; k < 8; k++) cp16(&buf[0][tid + 128 * k], s0 + tid + 128 * k, pol);
    CP_COMMIT();
    #pragma unroll
    for (int k = 0; k < 8; k++) cp16(&buf[1][tid + 128 * k], s1 + tid + 128 * k, pol);
    CP_COMMIT();

    CP_WAIT(1);
    __syncthreads();
    {
        const float4* vec = (t0 < 1024) ? svx : svh;
        float a = 0.f;
        #pragma unroll
        for (int k = 0; k < 8; k++) a += dot4(buf[0][warp * 256 + lane + 32 * k], vec[lane + 32 * k]);
        a = warp_sum(a);
        if (lane == 0) atomicAdd(&g_gates[(t0 * GT_TILE + warp) & 4095], a);
    }
    CP_WAIT(0);
    __syncthreads();
    {
        const float4* vec = (t1 < 1024) ? svx : svh;
        float a = 0.f;
        #pragma unroll
        for (int k = 0; k < 8; k++) a += dot4(buf[1][warp * 256 + lane + 32 * k], vec[lane + 32 * k]);
        a = warp_sum(a);
        if (lane == 0) atomicAdd(&g_gates[(t1 * GT_TILE + warp) & 4095], a);
    }
}

// ---------------------------------------------------------------------------
// LSTM pointwise: gates -> c_new, h_new
// ---------------------------------------------------------------------------
__global__ void k_lstm_pw(const float* __restrict__ c0,
                          float* __restrict__ h_out, float* __restrict__ c_out) {
    int j = blockIdx.x * 256 + threadIdx.x;
    float gi = g_gates[j], gf = g_gates[H + j], gg = g_gates[2 * H + j], go = g_gates[3 * H + j];
    float ig = 1.f / (1.f + expf(-gi));
    float fg = 1.f / (1.f + expf(-gf));
    float gt = tanhf(gg);
    float og = 1.f / (1.f + expf(-go));
    float cn = fg * c0[j] + ig * gt;
    float hn = og * tanhf(cn);
    c_out[j] = cn;
    h_out[j] = hn;
    g_h[j]   = hn;
}

// ---------------------------------------------------------------------------
// output projection: persistent 888 blocks, cp.async double-buffered 4-row
// tiles, online logsumexp per warp, fused last-block logZ. Raw logits -> out.
// ---------------------------------------------------------------------------
__device__ __forceinline__ void ot_issue(float4 (*buf)[OT_TILE * 256], int s, long t,
                                         const float* __restrict__ out_W,
                                         int tid, uint64_t pol) {
    #pragma unroll
    for (int k = 0; k < 8; k++) {
        int idx = tid + 128 * k;                 // 0..1023 float4 within tile
        long row = t * OT_TILE + (idx >> 8);
        if (row > V - 1) row = V - 1;
        cp16(&buf[s][idx], (const float4*)(out_W + row * (long)H) + (idx & 255), pol);
    }
    CP_COMMIT();
}

__global__ void __launch_bounds__(128) k_out(const float* __restrict__ out_W,
                                             const float* __restrict__ out_b,
                                             float* __restrict__ out) {
    __shared__ float4 buf[2][OT_TILE * 256];     // 2 x 16KB
    __shared__ float4 sh4[256];
    __shared__ float  sm_m[4], sm_s[4];
    int tid = threadIdx.x, warp = tid >> 5, lane = tid & 31;
    uint64_t pol = mkpolicy();

    sh4[tid]       = ((const float4*)g_h)[tid];
    sh4[tid + 128] = ((const float4*)g_h)[tid + 128];

    int nt = (OT_NT - blockIdx.x + OT_GRID - 1) / OT_GRID;

    if (nt > 0) ot_issue(buf, 0, (long)blockIdx.x, out_W, tid, pol);
    if (nt > 1) ot_issue(buf, 1, blockIdx.x + (long)OT_GRID, out_W, tid, pol);

    float m = -INFINITY, ssum = 0.f;
    for (int i = 0; i < nt; i++) {
        if (nt - 1 - i >= 1) { CP_WAIT(1); } else { CP_WAIT(0); }
        __syncthreads();
        int s = i & 1;
        long row = (blockIdx.x + (long)i * OT_GRID) * OT_TILE + warp;
        float a = 0.f;
        #pragma unroll
        for (int k = 0; k < 8; k++)
            a += dot4(buf[s][warp * 256 + lane + 32 * k], sh4[lane + 32 * k]);
        a = warp_sum(a);
        if (lane == 0 && row < V) {
            float lg = a + out_b[row];
            out[row] = lg;
            if (lg > m) { ssum = ssum * expf(m - lg) + 1.f; m = lg; }
            else        { ssum += expf(lg - m); }
        }
        __syncthreads();
        if (i + 2 < nt) ot_issue(buf, s, blockIdx.x + (long)(i + 2) * OT_GRID, out_W, tid, pol);
    }

    if (lane == 0) { sm_m[warp] = m; sm_s[warp] = ssum; }
    __syncthreads();
    __shared__ unsigned is_last;
    if (tid == 0) {
        float M = sm_m[0];
        #pragma unroll
        for (int k = 1; k < 4; k++) M = fmaxf(M, sm_m[k]);
        float S = 0.f;
        #pragma unroll
        for (int k = 0; k < 4; k++) S += sm_s[k] * expf(sm_m[k] - M);
        g_bmax[blockIdx.x] = M;
        g_bsum[blockIdx.x] = S;
        __threadfence();
        is_last = (atomicAdd(&g_ctr_out, 1u) == OT_GRID - 1);
    }
    __syncthreads();
    if (!is_last) return;

    __threadfence();
    float mm = -INFINITY;
    for (int k = tid; k < OT_GRID; k += 128) mm = fmaxf(mm, g_bmax[k]);
    __shared__ float red[4];
    mm = warp_max(mm);
    if (lane == 0) red[warp] = mm;
    __syncthreads();
    if (tid == 0) {
        float z = red[0];
        #pragma unroll
        for (int k = 1; k < 4; k++) z = fmaxf(z, red[k]);
        red[0] = z;
    }
    __syncthreads();
    float M = red[0];
    __syncthreads();
    float S = 0.f;
    for (int k = tid; k < OT_GRID; k += 128) S += g_bsum[k] * expf(g_bmax[k] - M);
    S = warp_sum(S);
    if (lane == 0) red[warp] = S;
    __syncthreads();
    if (tid == 0) {
        float z = red[0] + red[1] + red[2] + red[3];
        g_logZ = M + logf(z);
        g_ctr_out = 0;
    }
}

__global__ void k_final(float* __restrict__ out) {
    int v = blockIdx.x * blockDim.x + threadIdx.x;
    if (v >= V) return;
    out[v] -= g_logZ;
}

extern "C" void kernel_launch(void* const* d_in, const int* in_sizes, int n_in,
                              void* d_out, int out_size) {
    const int*   tokens = (const int*)  d_in[0];
    const float* h0     = (const float*)d_in[1];
    const float* c0     = (const float*)d_in[2];
    const float* enc    = (const float*)d_in[3];
    const float* emb    = (const float*)d_in[4];
    const float* attn_W = (const float*)d_in[5];
    const float* attn_b = (const float*)d_in[6];
    const float* comb_W = (const float*)d_in[7];
    const float* comb_b = (const float*)d_in[8];
    const float* W_ih   = (const float*)d_in[9];
    const float* W_hh   = (const float*)d_in[10];
    const float* b_ih   = (const float*)d_in[11];
    const float* b_hh   = (const float*)d_in[12];
    const float* out_W  = (const float*)d_in[13];
    const float* out_b  = (const float*)d_in[14];

    float* out    = (float*)d_out;          // [V] log-probs
    float* h_out  = out + V;                // [H]
    float* c_out  = out + V + H;            // [H]
    float* aw_out = out + V + 2 * H;        // [L]

    k_attn        <<<L, 256>>>(tokens, emb, h0, attn_W, attn_b, aw_out);
    k_attn_applied<<<H / 32, 256>>>(enc);
    k_comb        <<<H / 8, 256>>>(tokens, emb, comb_W, comb_b, b_ih, b_hh);
    k_gates       <<<GT_TILES / 2, 128>>>(W_ih, W_hh, h0);
    k_lstm_pw     <<<H / 256, 256>>>(c0, h_out, c_out);
    k_out         <<<OT_GRID, 128>>>(out_W, out_b, out);
    k_final       <<<(V + 511) / 512, 512>>>(out);
}